// round 13
// baseline (speedup 1.0000x reference)
#include <cuda_runtime.h>
#include <cuda_fp16.h>
#include <stdint.h>

// ---------------- Problem shape ----------------
#define BB 8
#define NN 3136
#define DD 1536
#define PP 4096
#define MM (BB*NN)          // 25088

// ---------------- Tiling ----------------
#define BM 128
#define BN 128
#define BK 64               // fp16 per k-chunk (128 B rows)
#define NKC (DD/BK)         // 24 (EVEN: buffer parity is continuous across items)
#define NMT (MM/BM)         // 196
#define NNT (PP/BN)         // 32
#define NITEMS (NMT*NNT)    // 6272
#define GRID 444            // 3 persistent CTAs per SM
#define THREADS 256

#define SMEM_BYTES (2*BM*64*2 + 2*BN*64*2)   // 65536 (2-stage A+B) -> 192KB/SM

// ---------------- Scratch (device globals: allocation-free rule) ------------
__device__ __half g_A[(size_t)MM*DD];          // embeds f16
__device__ __half g_Bc[(size_t)PP*DD];         // centroids f16
__device__ float g_nA[MM];                     // ||x||^2 (fp32 from fp32 inputs)
__device__ float g_nB[PP];                     // ||c||^2
__device__ unsigned int g_min[MM];             // running min of dist^2 (uint bits)

// ---------------------------------------------------------------------------
// Prep: fp32 -> fp16 (vectorized) + fp32 squared norms + g_min init.
// ---------------------------------------------------------------------------
#define PT 128
__global__ void prep_kernel(const float* __restrict__ embeds,
                            const float* __restrict__ cents,
                            float* __restrict__ out, int loss_elems) {
    int row = blockIdx.x;
    const float4* src;
    uint2* dst;
    float* ndst;
    if (row < MM) {
        src = (const float4*)(embeds + (size_t)row * DD);
        dst = (uint2*)(g_A + (size_t)row * DD);
        ndst = g_nA + row;
        if (threadIdx.x == 0) g_min[row] = 0x7F800000u;  // +inf
    } else {
        int r = row - MM;
        src = (const float4*)(cents + (size_t)r * DD);
        dst = (uint2*)(g_Bc + (size_t)r * DD);
        ndst = g_nB + r;
    }
    float s = 0.f;
#pragma unroll
    for (int i = 0; i < DD / 4 / PT; ++i) {
        int j = i * PT + threadIdx.x;
        float4 v = src[j];
        __half2 lo = __floats2half2_rn(v.x, v.y);
        __half2 hi = __floats2half2_rn(v.z, v.w);
        uint2 pk;
        pk.x = *(uint32_t*)&lo;
        pk.y = *(uint32_t*)&hi;
        dst[j] = pk;
        s += v.x * v.x + v.y * v.y + v.z * v.z + v.w * v.w;
    }
#pragma unroll
    for (int off = 16; off; off >>= 1)
        s += __shfl_xor_sync(0xffffffffu, s, off);
    __shared__ float ws[PT / 32];
    int lane = threadIdx.x & 31, warp = threadIdx.x >> 5;
    if (lane == 0) ws[warp] = s;
    __syncthreads();
    if (threadIdx.x == 0) {
        float t = 0.f;
#pragma unroll
        for (int w = 0; w < PT / 32; ++w) t += ws[w];
        *ndst = t;
    }
    if (row == 0 && threadIdx.x < loss_elems) out[threadIdx.x] = 0.f;
}

// ---------------------------------------------------------------------------
// PTX helpers (generic ISA only)
// ---------------------------------------------------------------------------
__device__ __forceinline__ uint32_t smem_u32(const void* p) {
    return (uint32_t)__cvta_generic_to_shared(p);
}
__device__ __forceinline__ void cp16(void* s, const void* g) {
    asm volatile("cp.async.cg.shared.global [%0], [%1], 16;\n"
                 :: "r"(smem_u32(s)), "l"(g));
}
__device__ __forceinline__ void cp_commit() {
    asm volatile("cp.async.commit_group;\n");
}
template <int N>
__device__ __forceinline__ void cp_wait() {
    asm volatile("cp.async.wait_group %0;\n" :: "n"(N));
}
__device__ __forceinline__ void ldm_x4(uint32_t* r, const __half* p) {
    asm volatile("ldmatrix.sync.aligned.m8n8.x4.shared.b16 {%0,%1,%2,%3}, [%4];\n"
                 : "=r"(r[0]), "=r"(r[1]), "=r"(r[2]), "=r"(r[3])
                 : "r"(smem_u32(p)));
}
__device__ __forceinline__ void mma_f16(uint32_t* c, const uint32_t* a,
                                        const uint32_t* b) {
    asm volatile("mma.sync.aligned.m16n8k16.row.col.f16.f16.f16.f16 "
                 "{%0,%1}, {%2,%3,%4,%5}, {%6,%7}, {%0,%1};\n"
                 : "+r"(c[0]), "+r"(c[1])
                 : "r"(a[0]), "r"(a[1]), "r"(a[2]), "r"(a[3]),
                   "r"(b[0]), "r"(b[1]));
}
// XOR-swizzled half offset for (row, 16B-chunk c8) in a [rows][64]-half tile.
__device__ __forceinline__ int swz(int row, int c8) {
    return row * 64 + ((c8 ^ (row & 7)) << 3);
}

// ---------------------------------------------------------------------------
// Persistent HMMA(f16-acc) GEMM-min. 444 CTAs, 3/SM, 6272 items.
// Single barrier per k-chunk AND a continuous cross-item chunk stream:
// the prefetch pointer walks (item, kc) pairs past item boundaries, so the
// 2-buffer cp.async ring never drains for the CTA's whole lifetime; the
// epilogue (registers + L2 only) overlaps the next item's first loads.
// ---------------------------------------------------------------------------
__device__ __forceinline__ void issue_chunk(__half* As, __half* Bs, int buf,
                                            int item, int kc, int tid) {
    const int m0 = (item >> 5) * BM;
    const int p0 = (item & 31) * BN;
    const __half* Ag = g_A + (size_t)m0 * DD + kc * BK;
    const __half* Bg = g_Bc + (size_t)p0 * DD + kc * BK;
    __half* Asb = As + buf * BM * 64;
    __half* Bsb = Bs + buf * BN * 64;
#pragma unroll
    for (int t = 0; t < 4; ++t) {
        int idx = tid + t * THREADS;
        int row = idx >> 3, c8 = idx & 7;
        cp16(Asb + swz(row, c8), Ag + (size_t)row * DD + c8 * 8);
        cp16(Bsb + swz(row, c8), Bg + (size_t)row * DD + c8 * 8);
    }
}

__global__ __launch_bounds__(THREADS, 3)
void gemm_min_kernel() {
    extern __shared__ __align__(16) char smem_raw[];
    __half* As = (__half*)smem_raw;                   // 2 x [128][64]
    __half* Bs = As + 2 * BM * 64;                    // 2 x [128][64]

    const int tid = threadIdx.x;
    const int lane = tid & 31, warp = tid >> 5;
    const int wm = warp >> 1, wn = warp & 1;          // 4(M) x 2(N) warps

    const int arow  = (lane & 7) + ((lane >> 3) & 1) * 8;
    const int acbit = (lane >> 4) & 1;

    // prefetch pointer: one chunk ahead of compute, crosses item boundaries
    int pf_it = blockIdx.x, pf_kc = 0;
    issue_chunk(As, Bs, 0, pf_it, 0, tid);
    cp_commit();
    pf_kc = 1;

    for (int it = blockIdx.x; it < NITEMS; it += GRID) {
        const int m0 = (it >> 5) * BM;
        const int p0 = (it & 31) * BN;

        uint32_t acc[2][8][2];                        // f16x2 accumulators
#pragma unroll
        for (int i = 0; i < 2; ++i)
#pragma unroll
            for (int j = 0; j < 8; ++j) { acc[i][j][0] = 0u; acc[i][j][1] = 0u; }

#pragma unroll 1
        for (int kc = 0; kc < NKC; ++kc) {
            cp_wait<0>();          // chunk kc fully arrived
            __syncthreads();       // all warps done reading buffer (kc-1)&1

            if (pf_it < NITEMS) {  // prefetch next stream chunk into that buffer
                issue_chunk(As, Bs, (kc + 1) & 1, pf_it, pf_kc, tid);
                cp_commit();
                if (++pf_kc == NKC) { pf_kc = 0; pf_it += GRID; }
            }

            const __half* Asb = As + (kc & 1) * BM * 64;
            const __half* Bsb = Bs + (kc & 1) * BN * 64;
#pragma unroll
            for (int ks = 0; ks < BK / 16; ++ks) {
                uint32_t a[2][4];
                int c8 = ks * 2 + acbit;
#pragma unroll
                for (int mt = 0; mt < 2; ++mt) {
                    int row = wm * 32 + mt * 16 + arow;
                    ldm_x4(a[mt], Asb + swz(row, c8));
                }
                uint32_t b[8][2];
#pragma unroll
                for (int tp = 0; tp < 4; ++tp) {
                    uint32_t r[4];
                    int row = wn * 64 + tp * 16 + arow;
                    ldm_x4(r, Bsb + swz(row, c8));
                    b[2 * tp][0] = r[0];  b[2 * tp][1] = r[2];
                    b[2 * tp + 1][0] = r[1]; b[2 * tp + 1][1] = r[3];
                }
#pragma unroll
                for (int mt = 0; mt < 2; ++mt)
#pragma unroll
                    for (int j = 0; j < 8; ++j)
                        mma_f16(acc[mt][j], a[mt], b[j]);
            }
            // no trailing barrier: next chunk's top barrier provides safety
        }

        // epilogue (regs + L2 only — overlaps next item's in-flight loads)
        float rmin[2][2] = {{3.4e38f, 3.4e38f}, {3.4e38f, 3.4e38f}};
#pragma unroll
        for (int j = 0; j < 8; ++j) {
            int col = p0 + wn * 64 + j * 8 + (lane & 3) * 2;
            float nc0 = g_nB[col], nc1 = g_nB[col + 1];
#pragma unroll
            for (int mt = 0; mt < 2; ++mt) {
                float2 lo = __half22float2(*(__half2*)&acc[mt][j][0]); // row r
                float2 hi = __half22float2(*(__half2*)&acc[mt][j][1]); // row r+8
                float v0 = fminf(nc0 - 2.f * lo.x, nc1 - 2.f * lo.y);
                float v1 = fminf(nc0 - 2.f * hi.x, nc1 - 2.f * hi.y);
                rmin[mt][0] = fminf(rmin[mt][0], v0);
                rmin[mt][1] = fminf(rmin[mt][1], v1);
            }
        }
#pragma unroll
        for (int mt = 0; mt < 2; ++mt)
#pragma unroll
            for (int h = 0; h < 2; ++h) {
                float v = rmin[mt][h];
                v = fminf(v, __shfl_xor_sync(0xffffffffu, v, 1));
                v = fminf(v, __shfl_xor_sync(0xffffffffu, v, 2));
                rmin[mt][h] = v;
            }
        if ((lane & 3) == 0) {
            int q = lane >> 2;
#pragma unroll
            for (int mt = 0; mt < 2; ++mt)
#pragma unroll
                for (int h = 0; h < 2; ++h) {
                    int m = m0 + wm * 32 + mt * 16 + h * 8 + q;
                    float d2 = fmaxf(g_nA[m] + rmin[mt][h], 0.f);
                    atomicMin(&g_min[m], __float_as_uint(d2));
                }
        }
    }
}

// ---------------------------------------------------------------------------
// Final: sqrt of the folded min distance^2.
// ---------------------------------------------------------------------------
__global__ void sqrt_kernel(float* __restrict__ out, int offset) {
    int m = blockIdx.x * blockDim.x + threadIdx.x;
    if (m < MM) out[offset + m] = sqrtf(__uint_as_float(g_min[m]));
}

// ---------------------------------------------------------------------------
extern "C" void kernel_launch(void* const* d_in, const int* in_sizes, int n_in,
                              void* d_out, int out_size) {
    const float* embeds = (const float*)d_in[0];
    const float* cents  = (const float*)d_in[1];
    if (n_in >= 2 && in_sizes[0] == PP * DD && in_sizes[1] == MM * DD) {
        embeds = (const float*)d_in[1];
        cents  = (const float*)d_in[0];
    }
    float* out = (float*)d_out;
    int loss_elems = out_size - MM;
    if (loss_elems < 0) loss_elems = 0;

    cudaFuncSetAttribute(gemm_min_kernel,
                         cudaFuncAttributeMaxDynamicSharedMemorySize, SMEM_BYTES);

    prep_kernel<<<MM + PP, PT>>>(embeds, cents, out, loss_elems);
    gemm_min_kernel<<<GRID, THREADS, SMEM_BYTES>>>();
    sqrt_kernel<<<(MM + 255) / 256, 256>>>(out, loss_elems);
}

// round 14
// speedup vs baseline: 1.0249x; 1.0249x over previous
#include <cuda_runtime.h>
#include <cuda_fp16.h>
#include <stdint.h>

// ---------------- Problem shape ----------------
#define BB 8
#define NN 3136
#define DD 1536
#define PP 4096
#define MM (BB*NN)          // 25088

// ---------------- Tiling ----------------
#define BM 128
#define BN 128
#define BK 64               // fp16 per k-chunk (128 B rows)
#define NKC (DD/BK)         // 24
#define NMT (MM/BM)         // 196
#define NNT (PP/BN)         // 32
#define NITEMS (NMT*NNT)    // 6272
#define GRID 444            // 3 persistent CTAs per SM
#define THREADS 256

#define SMEM_BYTES (2*BM*64*2 + 2*BN*64*2)   // 65536 (2-stage A+B) -> 192KB/SM

// ---------------- Scratch (device globals: allocation-free rule) ------------
__device__ __half g_A[(size_t)MM*DD];          // embeds f16
__device__ __half g_Bc[(size_t)PP*DD];         // centroids f16
__device__ float g_nA[MM];                     // ||x||^2 (fp32 from fp32 inputs)
__device__ float g_nB[PP];                     // ||c||^2
__device__ unsigned int g_min[MM];             // running min of dist^2 (uint bits)

// ---------------------------------------------------------------------------
// Prep: fp32 -> fp16 (vectorized) + fp32 squared norms + g_min init.
// ---------------------------------------------------------------------------
#define PT 128
__global__ void prep_kernel(const float* __restrict__ embeds,
                            const float* __restrict__ cents,
                            float* __restrict__ out, int loss_elems) {
    int row = blockIdx.x;
    const float4* src;
    uint2* dst;
    float* ndst;
    if (row < MM) {
        src = (const float4*)(embeds + (size_t)row * DD);
        dst = (uint2*)(g_A + (size_t)row * DD);
        ndst = g_nA + row;
        if (threadIdx.x == 0) g_min[row] = 0x7F800000u;  // +inf
    } else {
        int r = row - MM;
        src = (const float4*)(cents + (size_t)r * DD);
        dst = (uint2*)(g_Bc + (size_t)r * DD);
        ndst = g_nB + r;
    }
    float s = 0.f;
#pragma unroll
    for (int i = 0; i < DD / 4 / PT; ++i) {
        int j = i * PT + threadIdx.x;
        float4 v = src[j];
        __half2 lo = __floats2half2_rn(v.x, v.y);
        __half2 hi = __floats2half2_rn(v.z, v.w);
        uint2 pk;
        pk.x = *(uint32_t*)&lo;
        pk.y = *(uint32_t*)&hi;
        dst[j] = pk;
        s += v.x * v.x + v.y * v.y + v.z * v.z + v.w * v.w;
    }
#pragma unroll
    for (int off = 16; off; off >>= 1)
        s += __shfl_xor_sync(0xffffffffu, s, off);
    __shared__ float ws[PT / 32];
    int lane = threadIdx.x & 31, warp = threadIdx.x >> 5;
    if (lane == 0) ws[warp] = s;
    __syncthreads();
    if (threadIdx.x == 0) {
        float t = 0.f;
#pragma unroll
        for (int w = 0; w < PT / 32; ++w) t += ws[w];
        *ndst = t;
    }
    if (row == 0 && threadIdx.x < loss_elems) out[threadIdx.x] = 0.f;
}

// ---------------------------------------------------------------------------
// PTX helpers (generic ISA only)
// ---------------------------------------------------------------------------
__device__ __forceinline__ uint32_t smem_u32(const void* p) {
    return (uint32_t)__cvta_generic_to_shared(p);
}
__device__ __forceinline__ void cp16(void* s, const void* g) {
    asm volatile("cp.async.cg.shared.global [%0], [%1], 16;\n"
                 :: "r"(smem_u32(s)), "l"(g));
}
__device__ __forceinline__ void cp_commit() {
    asm volatile("cp.async.commit_group;\n");
}
template <int N>
__device__ __forceinline__ void cp_wait() {
    asm volatile("cp.async.wait_group %0;\n" :: "n"(N));
}
__device__ __forceinline__ void ldm_x4(uint32_t* r, const __half* p) {
    asm volatile("ldmatrix.sync.aligned.m8n8.x4.shared.b16 {%0,%1,%2,%3}, [%4];\n"
                 : "=r"(r[0]), "=r"(r[1]), "=r"(r[2]), "=r"(r[3])
                 : "r"(smem_u32(p)));
}
__device__ __forceinline__ void mma_f16(uint32_t* c, const uint32_t* a,
                                        const uint32_t* b) {
    asm volatile("mma.sync.aligned.m16n8k16.row.col.f16.f16.f16.f16 "
                 "{%0,%1}, {%2,%3,%4,%5}, {%6,%7}, {%0,%1};\n"
                 : "+r"(c[0]), "+r"(c[1])
                 : "r"(a[0]), "r"(a[1]), "r"(a[2]), "r"(a[3]),
                   "r"(b[0]), "r"(b[1]));
}
// XOR-swizzled half offset for (row, 16B-chunk c8) in a [rows][64]-half tile.
__device__ __forceinline__ int swz(int row, int c8) {
    return row * 64 + ((c8 ^ (row & 7)) << 3);
}

// ---------------------------------------------------------------------------
// Persistent HMMA(f16-acc) GEMM-min. 444 CTAs, 3/SM, 6272 items.
// Single barrier per chunk (R12 structure) + HOISTED cp.async addressing:
// the per-thread smem swizzle offset is constant (row&7 invariant under +32
// row steps), and global pointers advance by compile-time strides, so the
// per-chunk issue path is just 8 adds + 8 cp.asyncs per thread.
// ---------------------------------------------------------------------------
__global__ __launch_bounds__(THREADS, 3)
void gemm_min_kernel() {
    extern __shared__ __align__(16) char smem_raw[];
    __half* As = (__half*)smem_raw;                   // 2 x [128][64]
    __half* Bs = As + 2 * BM * 64;                    // 2 x [128][64]

    const int tid = threadIdx.x;
    const int lane = tid & 31, warp = tid >> 5;
    const int wm = warp >> 1, wn = warp & 1;          // 4(M) x 2(N) warps

    const int arow  = (lane & 7) + ((lane >> 3) & 1) * 8;
    const int acbit = (lane >> 4) & 1;

    // ---- hoisted producer addressing (constant for the whole kernel) ----
    const int c8p  = tid & 7;            // 16B chunk within a 128B row
    const int rp0  = tid >> 3;           // first of 4 rows (stride 32)
    const int offP = swz(rp0, c8p);      // smem half-offset; +2048 per row step
    __half* const dA0 = As + offP;       // buffer 0 targets
    __half* const dB0 = Bs + offP;

    for (int it = blockIdx.x; it < NITEMS; it += GRID) {
        const int m0 = (it >> 5) * BM;
        const int p0 = (it & 31) * BN;

        // per-item global bases for this thread's 4 rows (stride 32*DD)
        const __half* const aBase = g_A  + (size_t)(m0 + rp0) * DD + c8p * 8;
        const __half* const bBase = g_Bc + (size_t)(p0 + rp0) * DD + c8p * 8;

        uint32_t acc[2][8][2];                        // f16x2 accumulators
#pragma unroll
        for (int i = 0; i < 2; ++i)
#pragma unroll
            for (int j = 0; j < 8; ++j) { acc[i][j][0] = 0u; acc[i][j][1] = 0u; }

        // prologue: chunk 0 -> buffer 0
#pragma unroll
        for (int t = 0; t < 4; ++t) {
            cp16(dA0 + t * 2048, aBase + (size_t)t * 32 * DD);
            cp16(dB0 + t * 2048, bBase + (size_t)t * 32 * DD);
        }
        cp_commit();

#pragma unroll 1
        for (int kc = 0; kc < NKC; ++kc) {
            cp_wait<0>();          // chunk kc fully arrived
            __syncthreads();       // all warps done reading buffer (kc-1)&1

            if (kc + 1 < NKC) {    // prefetch kc+1 into that now-free buffer
                const int bufo = ((kc + 1) & 1) * (BM * 64);
                const __half* a = aBase + (kc + 1) * BK;
                const __half* b = bBase + (kc + 1) * BK;
#pragma unroll
                for (int t = 0; t < 4; ++t) {
                    cp16(dA0 + bufo + t * 2048, a + (size_t)t * 32 * DD);
                    cp16(dB0 + bufo + t * 2048, b + (size_t)t * 32 * DD);
                }
                cp_commit();
            }

            const __half* Asb = As + (kc & 1) * BM * 64;
            const __half* Bsb = Bs + (kc & 1) * BN * 64;
#pragma unroll
            for (int ks = 0; ks < BK / 16; ++ks) {
                uint32_t a[2][4];
                int c8 = ks * 2 + acbit;
#pragma unroll
                for (int mt = 0; mt < 2; ++mt) {
                    int row = wm * 32 + mt * 16 + arow;
                    ldm_x4(a[mt], Asb + swz(row, c8));
                }
                uint32_t b[8][2];
#pragma unroll
                for (int tp = 0; tp < 4; ++tp) {
                    uint32_t r[4];
                    int row = wn * 64 + tp * 16 + arow;
                    ldm_x4(r, Bsb + swz(row, c8));
                    b[2 * tp][0] = r[0];  b[2 * tp][1] = r[2];
                    b[2 * tp + 1][0] = r[1]; b[2 * tp + 1][1] = r[3];
                }
#pragma unroll
                for (int mt = 0; mt < 2; ++mt)
#pragma unroll
                    for (int j = 0; j < 8; ++j)
                        mma_f16(acc[mt][j], a[mt], b[j]);
            }
            // no trailing barrier: next chunk's top barrier provides safety
        }

        // epilogue: unpack f16x2 accs, min over warp's 64 cols, atomicMin
        float rmin[2][2] = {{3.4e38f, 3.4e38f}, {3.4e38f, 3.4e38f}};
#pragma unroll
        for (int j = 0; j < 8; ++j) {
            int col = p0 + wn * 64 + j * 8 + (lane & 3) * 2;
            float nc0 = g_nB[col], nc1 = g_nB[col + 1];
#pragma unroll
            for (int mt = 0; mt < 2; ++mt) {
                float2 lo = __half22float2(*(__half2*)&acc[mt][j][0]); // row r
                float2 hi = __half22float2(*(__half2*)&acc[mt][j][1]); // row r+8
                float v0 = fminf(nc0 - 2.f * lo.x, nc1 - 2.f * lo.y);
                float v1 = fminf(nc0 - 2.f * hi.x, nc1 - 2.f * hi.y);
                rmin[mt][0] = fminf(rmin[mt][0], v0);
                rmin[mt][1] = fminf(rmin[mt][1], v1);
            }
        }
#pragma unroll
        for (int mt = 0; mt < 2; ++mt)
#pragma unroll
            for (int h = 0; h < 2; ++h) {
                float v = rmin[mt][h];
                v = fminf(v, __shfl_xor_sync(0xffffffffu, v, 1));
                v = fminf(v, __shfl_xor_sync(0xffffffffu, v, 2));
                rmin[mt][h] = v;
            }
        if ((lane & 3) == 0) {
            int q = lane >> 2;
#pragma unroll
            for (int mt = 0; mt < 2; ++mt)
#pragma unroll
                for (int h = 0; h < 2; ++h) {
                    int m = m0 + wm * 32 + mt * 16 + h * 8 + q;
                    float d2 = fmaxf(g_nA[m] + rmin[mt][h], 0.f);
                    atomicMin(&g_min[m], __float_as_uint(d2));
                }
        }
    }
}

// ---------------------------------------------------------------------------
// Final: sqrt of the folded min distance^2.
// ---------------------------------------------------------------------------
__global__ void sqrt_kernel(float* __restrict__ out, int offset) {
    int m = blockIdx.x * blockDim.x + threadIdx.x;
    if (m < MM) out[offset + m] = sqrtf(__uint_as_float(g_min[m]));
}

// ---------------------------------------------------------------------------
extern "C" void kernel_launch(void* const* d_in, const int* in_sizes, int n_in,
                              void* d_out, int out_size) {
    const float* embeds = (const float*)d_in[0];
    const float* cents  = (const float*)d_in[1];
    if (n_in >= 2 && in_sizes[0] == PP * DD && in_sizes[1] == MM * DD) {
        embeds = (const float*)d_in[1];
        cents  = (const float*)d_in[0];
    }
    float* out = (float*)d_out;
    int loss_elems = out_size - MM;
    if (loss_elems < 0) loss_elems = 0;

    cudaFuncSetAttribute(gemm_min_kernel,
                         cudaFuncAttributeMaxDynamicSharedMemorySize, SMEM_BYTES);

    prep_kernel<<<MM + PP, PT>>>(embeds, cents, out, loss_elems);
    gemm_min_kernel<<<GRID, THREADS, SMEM_BYTES>>>();
    sqrt_kernel<<<(MM + 255) / 256, 256>>>(out, loss_elems);
}

// round 15
// speedup vs baseline: 1.0508x; 1.0252x over previous
#include <cuda_runtime.h>
#include <cuda_fp16.h>
#include <stdint.h>

// ---------------- Problem shape ----------------
#define BB 8
#define NN 3136
#define DD 1536
#define PP 4096
#define MM (BB*NN)          // 25088

// ---------------- Tiling ----------------
#define BM 128
#define BN 128
#define BK 64               // fp16 per k-chunk (128 B rows)
#define NKC (DD/BK)         // 24
#define NMT (MM/BM)         // 196
#define NNT (PP/BN)         // 32
#define NITEMS (NMT*NNT)    // 6272
#define GRID 444            // 3 persistent CTAs per SM
#define THREADS 256

#define SMEM_BYTES (2*BM*64*2 + 2*BN*64*2)   // 65536 (2-stage A+B) -> 192KB/SM

// ---------------- Scratch (device globals: allocation-free rule) ------------
__device__ __half g_A[(size_t)MM*DD];          // embeds f16
__device__ __half g_Bc[(size_t)PP*DD];         // centroids f16
__device__ float g_nA[MM];                     // ||x||^2 (fp32 from fp32 inputs)
__device__ float g_nB[PP];                     // ||c||^2
__device__ unsigned int g_min[MM];             // running min of dist^2 (uint bits)

// ---------------------------------------------------------------------------
// Prep: fp32 -> fp16 (vectorized) + fp32 squared norms + g_min init.
// ---------------------------------------------------------------------------
#define PT 128
__global__ void prep_kernel(const float* __restrict__ embeds,
                            const float* __restrict__ cents,
                            float* __restrict__ out, int loss_elems) {
    int row = blockIdx.x;
    const float4* src;
    uint2* dst;
    float* ndst;
    if (row < MM) {
        src = (const float4*)(embeds + (size_t)row * DD);
        dst = (uint2*)(g_A + (size_t)row * DD);
        ndst = g_nA + row;
        if (threadIdx.x == 0) g_min[row] = 0x7F800000u;  // +inf
    } else {
        int r = row - MM;
        src = (const float4*)(cents + (size_t)r * DD);
        dst = (uint2*)(g_Bc + (size_t)r * DD);
        ndst = g_nB + r;
    }
    float s = 0.f;
#pragma unroll
    for (int i = 0; i < DD / 4 / PT; ++i) {
        int j = i * PT + threadIdx.x;
        float4 v = src[j];
        __half2 lo = __floats2half2_rn(v.x, v.y);
        __half2 hi = __floats2half2_rn(v.z, v.w);
        uint2 pk;
        pk.x = *(uint32_t*)&lo;
        pk.y = *(uint32_t*)&hi;
        dst[j] = pk;
        s += v.x * v.x + v.y * v.y + v.z * v.z + v.w * v.w;
    }
#pragma unroll
    for (int off = 16; off; off >>= 1)
        s += __shfl_xor_sync(0xffffffffu, s, off);
    __shared__ float ws[PT / 32];
    int lane = threadIdx.x & 31, warp = threadIdx.x >> 5;
    if (lane == 0) ws[warp] = s;
    __syncthreads();
    if (threadIdx.x == 0) {
        float t = 0.f;
#pragma unroll
        for (int w = 0; w < PT / 32; ++w) t += ws[w];
        *ndst = t;
    }
    if (row == 0 && threadIdx.x < loss_elems) out[threadIdx.x] = 0.f;
}

// ---------------------------------------------------------------------------
// PTX helpers (generic ISA only)
// ---------------------------------------------------------------------------
__device__ __forceinline__ uint32_t smem_u32(const void* p) {
    return (uint32_t)__cvta_generic_to_shared(p);
}
__device__ __forceinline__ void cp16(void* s, const void* g) {
    asm volatile("cp.async.cg.shared.global [%0], [%1], 16;\n"
                 :: "r"(smem_u32(s)), "l"(g));
}
__device__ __forceinline__ void cp_commit() {
    asm volatile("cp.async.commit_group;\n");
}
template <int N>
__device__ __forceinline__ void cp_wait() {
    asm volatile("cp.async.wait_group %0;\n" :: "n"(N));
}
__device__ __forceinline__ void ldm_x4(uint32_t* r, const __half* p) {
    asm volatile("ldmatrix.sync.aligned.m8n8.x4.shared.b16 {%0,%1,%2,%3}, [%4];\n"
                 : "=r"(r[0]), "=r"(r[1]), "=r"(r[2]), "=r"(r[3])
                 : "r"(smem_u32(p)));
}
__device__ __forceinline__ void mma_f16(uint32_t* c, const uint32_t* a,
                                        const uint32_t* b) {
    asm volatile("mma.sync.aligned.m16n8k16.row.col.f16.f16.f16.f16 "
                 "{%0,%1}, {%2,%3,%4,%5}, {%6,%7}, {%0,%1};\n"
                 : "+r"(c[0]), "+r"(c[1])
                 : "r"(a[0]), "r"(a[1]), "r"(a[2]), "r"(a[3]),
                   "r"(b[0]), "r"(b[1]));
}
// XOR-swizzled half offset for (row, 16B-chunk c8) in a [rows][64]-half tile.
__device__ __forceinline__ int swz(int row, int c8) {
    return row * 64 + ((c8 ^ (row & 7)) << 3);
}

// ---------------------------------------------------------------------------
// Persistent HMMA(f16-acc) GEMM-min. 444 CTAs, 3/SM, 6272 items.
// R12 structure (single barrier/chunk, 2 buffers) with the prefetch issue
// MOVED between the ks=0 and ks=1 MMA groups: the ldmatrix->HMMA critical
// path starts immediately after the barrier, and the cp.async issue burst
// overlaps tensor-busy cycles instead of preceding them.
// ---------------------------------------------------------------------------
__device__ __forceinline__ void frags_step(uint32_t a[2][4], uint32_t b[8][2],
                                           const __half* Asb, const __half* Bsb,
                                           int ks, int wm, int wn,
                                           int arow, int acbit) {
    int c8 = ks * 2 + acbit;
#pragma unroll
    for (int mt = 0; mt < 2; ++mt) {
        int row = wm * 32 + mt * 16 + arow;
        ldm_x4(a[mt], Asb + swz(row, c8));
    }
#pragma unroll
    for (int tp = 0; tp < 4; ++tp) {
        uint32_t r[4];
        int row = wn * 64 + tp * 16 + arow;
        ldm_x4(r, Bsb + swz(row, c8));
        b[2 * tp][0] = r[0];  b[2 * tp][1] = r[2];
        b[2 * tp + 1][0] = r[1]; b[2 * tp + 1][1] = r[3];
    }
}

__global__ __launch_bounds__(THREADS, 3)
void gemm_min_kernel() {
    extern __shared__ __align__(16) char smem_raw[];
    __half* As = (__half*)smem_raw;                   // 2 x [128][64]
    __half* Bs = As + 2 * BM * 64;                    // 2 x [128][64]

    const int tid = threadIdx.x;
    const int lane = tid & 31, warp = tid >> 5;
    const int wm = warp >> 1, wn = warp & 1;          // 4(M) x 2(N) warps

    const int arow  = (lane & 7) + ((lane >> 3) & 1) * 8;
    const int acbit = (lane >> 4) & 1;

    // hoisted producer addressing
    const int c8p  = tid & 7;
    const int rp0  = tid >> 3;
    const int offP = swz(rp0, c8p);
    __half* const dA0 = As + offP;
    __half* const dB0 = Bs + offP;

    for (int it = blockIdx.x; it < NITEMS; it += GRID) {
        const int m0 = (it >> 5) * BM;
        const int p0 = (it & 31) * BN;

        const __half* const aBase = g_A  + (size_t)(m0 + rp0) * DD + c8p * 8;
        const __half* const bBase = g_Bc + (size_t)(p0 + rp0) * DD + c8p * 8;

        uint32_t acc[2][8][2];                        // f16x2 accumulators
#pragma unroll
        for (int i = 0; i < 2; ++i)
#pragma unroll
            for (int j = 0; j < 8; ++j) { acc[i][j][0] = 0u; acc[i][j][1] = 0u; }

        // prologue: chunk 0 -> buffer 0
#pragma unroll
        for (int t = 0; t < 4; ++t) {
            cp16(dA0 + t * 2048, aBase + (size_t)t * 32 * DD);
            cp16(dB0 + t * 2048, bBase + (size_t)t * 32 * DD);
        }
        cp_commit();

#pragma unroll 1
        for (int kc = 0; kc < NKC; ++kc) {
            cp_wait<0>();          // chunk kc fully arrived
            __syncthreads();       // all warps done reading buffer (kc-1)&1

            const __half* Asb = As + (kc & 1) * BM * 64;
            const __half* Bsb = Bs + (kc & 1) * BN * 64;

            // ks=0: start the tensor critical path FIRST
            uint32_t a[2][4], b[8][2];
            frags_step(a, b, Asb, Bsb, 0, wm, wn, arow, acbit);
#pragma unroll
            for (int mt = 0; mt < 2; ++mt)
#pragma unroll
                for (int j = 0; j < 8; ++j)
                    mma_f16(acc[mt][j], a[mt], b[j]);

            // prefetch kc+1 now — issue overlaps tensor-busy cycles
            if (kc + 1 < NKC) {
                const int bufo = ((kc + 1) & 1) * (BM * 64);
                const __half* ag = aBase + (kc + 1) * BK;
                const __half* bg = bBase + (kc + 1) * BK;
#pragma unroll
                for (int t = 0; t < 4; ++t) {
                    cp16(dA0 + bufo + t * 2048, ag + (size_t)t * 32 * DD);
                    cp16(dB0 + bufo + t * 2048, bg + (size_t)t * 32 * DD);
                }
                cp_commit();
            }

            // ks = 1..3
#pragma unroll
            for (int ks = 1; ks < BK / 16; ++ks) {
                frags_step(a, b, Asb, Bsb, ks, wm, wn, arow, acbit);
#pragma unroll
                for (int mt = 0; mt < 2; ++mt)
#pragma unroll
                    for (int j = 0; j < 8; ++j)
                        mma_f16(acc[mt][j], a[mt], b[j]);
            }
            // no trailing barrier: next chunk's top barrier provides safety
        }

        // epilogue: unpack f16x2 accs, min over warp's 64 cols, atomicMin
        float rmin[2][2] = {{3.4e38f, 3.4e38f}, {3.4e38f, 3.4e38f}};
#pragma unroll
        for (int j = 0; j < 8; ++j) {
            int col = p0 + wn * 64 + j * 8 + (lane & 3) * 2;
            float nc0 = g_nB[col], nc1 = g_nB[col + 1];
#pragma unroll
            for (int mt = 0; mt < 2; ++mt) {
                float2 lo = __half22float2(*(__half2*)&acc[mt][j][0]); // row r
                float2 hi = __half22float2(*(__half2*)&acc[mt][j][1]); // row r+8
                float v0 = fminf(nc0 - 2.f * lo.x, nc1 - 2.f * lo.y);
                float v1 = fminf(nc0 - 2.f * hi.x, nc1 - 2.f * hi.y);
                rmin[mt][0] = fminf(rmin[mt][0], v0);
                rmin[mt][1] = fminf(rmin[mt][1], v1);
            }
        }
#pragma unroll
        for (int mt = 0; mt < 2; ++mt)
#pragma unroll
            for (int h = 0; h < 2; ++h) {
                float v = rmin[mt][h];
                v = fminf(v, __shfl_xor_sync(0xffffffffu, v, 1));
                v = fminf(v, __shfl_xor_sync(0xffffffffu, v, 2));
                rmin[mt][h] = v;
            }
        if ((lane & 3) == 0) {
            int q = lane >> 2;
#pragma unroll
            for (int mt = 0; mt < 2; ++mt)
#pragma unroll
                for (int h = 0; h < 2; ++h) {
                    int m = m0 + wm * 32 + mt * 16 + h * 8 + q;
                    float d2 = fmaxf(g_nA[m] + rmin[mt][h], 0.f);
                    atomicMin(&g_min[m], __float_as_uint(d2));
                }
        }
    }
}

// ---------------------------------------------------------------------------
// Final: sqrt of the folded min distance^2.
// ---------------------------------------------------------------------------
__global__ void sqrt_kernel(float* __restrict__ out, int offset) {
    int m = blockIdx.x * blockDim.x + threadIdx.x;
    if (m < MM) out[offset + m] = sqrtf(__uint_as_float(g_min[m]));
}

// ---------------------------------------------------------------------------
extern "C" void kernel_launch(void* const* d_in, const int* in_sizes, int n_in,
                              void* d_out, int out_size) {
    const float* embeds = (const float*)d_in[0];
    const float* cents  = (const float*)d_in[1];
    if (n_in >= 2 && in_sizes[0] == PP * DD && in_sizes[1] == MM * DD) {
        embeds = (const float*)d_in[1];
        cents  = (const float*)d_in[0];
    }
    float* out = (float*)d_out;
    int loss_elems = out_size - MM;
    if (loss_elems < 0) loss_elems = 0;

    cudaFuncSetAttribute(gemm_min_kernel,
                         cudaFuncAttributeMaxDynamicSharedMemorySize, SMEM_BYTES);

    prep_kernel<<<MM + PP, PT>>>(embeds, cents, out, loss_elems);
    gemm_min_kernel<<<GRID, THREADS, SMEM_BYTES>>>();
    sqrt_kernel<<<(MM + 255) / 256, 256>>>(out, loss_elems);
}

// round 16
// speedup vs baseline: 1.0531x; 1.0022x over previous
#include <cuda_runtime.h>
#include <cuda_fp16.h>
#include <stdint.h>

// ---------------- Problem shape ----------------
#define BB 8
#define NN 3136
#define DD 1536
#define PP 4096
#define MM (BB*NN)          // 25088

// ---------------- Tiling ----------------
#define BM 128
#define BN 128
#define BK 64               // fp16 per k-chunk (128 B rows)
#define NKC (DD/BK)         // 24 (even: cross-item buffer parity works out)
#define NMT (MM/BM)         // 196
#define NNT (PP/BN)         // 32
#define NITEMS (NMT*NNT)    // 6272
#define GRID 444            // 3 persistent CTAs per SM
#define THREADS 256

#define SMEM_BYTES (2*BM*64*2 + 2*BN*64*2)   // 65536 (2-stage A+B) -> 192KB/SM

// ---------------- Scratch (device globals: allocation-free rule) ------------
__device__ __half g_A[(size_t)MM*DD];          // embeds f16
__device__ __half g_Bc[(size_t)PP*DD];         // centroids f16
__device__ float g_nA[MM];                     // ||x||^2 (fp32 from fp32 inputs)
__device__ float g_nB[PP];                     // ||c||^2
__device__ unsigned int g_min[MM];             // running min of dist^2 (uint bits)

// ---------------------------------------------------------------------------
// Prep: fp32 -> fp16 (vectorized) + fp32 squared norms + g_min init.
// ---------------------------------------------------------------------------
#define PT 128
__global__ void prep_kernel(const float* __restrict__ embeds,
                            const float* __restrict__ cents,
                            float* __restrict__ out, int loss_elems) {
    int row = blockIdx.x;
    const float4* src;
    uint2* dst;
    float* ndst;
    if (row < MM) {
        src = (const float4*)(embeds + (size_t)row * DD);
        dst = (uint2*)(g_A + (size_t)row * DD);
        ndst = g_nA + row;
        if (threadIdx.x == 0) g_min[row] = 0x7F800000u;  // +inf
    } else {
        int r = row - MM;
        src = (const float4*)(cents + (size_t)r * DD);
        dst = (uint2*)(g_Bc + (size_t)r * DD);
        ndst = g_nB + r;
    }
    float s = 0.f;
#pragma unroll
    for (int i = 0; i < DD / 4 / PT; ++i) {
        int j = i * PT + threadIdx.x;
        float4 v = src[j];
        __half2 lo = __floats2half2_rn(v.x, v.y);
        __half2 hi = __floats2half2_rn(v.z, v.w);
        uint2 pk;
        pk.x = *(uint32_t*)&lo;
        pk.y = *(uint32_t*)&hi;
        dst[j] = pk;
        s += v.x * v.x + v.y * v.y + v.z * v.z + v.w * v.w;
    }
#pragma unroll
    for (int off = 16; off; off >>= 1)
        s += __shfl_xor_sync(0xffffffffu, s, off);
    __shared__ float ws[PT / 32];
    int lane = threadIdx.x & 31, warp = threadIdx.x >> 5;
    if (lane == 0) ws[warp] = s;
    __syncthreads();
    if (threadIdx.x == 0) {
        float t = 0.f;
#pragma unroll
        for (int w = 0; w < PT / 32; ++w) t += ws[w];
        *ndst = t;
    }
    if (row == 0 && threadIdx.x < loss_elems) out[threadIdx.x] = 0.f;
}

// ---------------------------------------------------------------------------
// PTX helpers (generic ISA only)
// ---------------------------------------------------------------------------
__device__ __forceinline__ uint32_t smem_u32(const void* p) {
    return (uint32_t)__cvta_generic_to_shared(p);
}
__device__ __forceinline__ void cp16(void* s, const void* g) {
    asm volatile("cp.async.cg.shared.global [%0], [%1], 16;\n"
                 :: "r"(smem_u32(s)), "l"(g));
}
__device__ __forceinline__ void cp_commit() {
    asm volatile("cp.async.commit_group;\n");
}
template <int N>
__device__ __forceinline__ void cp_wait() {
    asm volatile("cp.async.wait_group %0;\n" :: "n"(N));
}
__device__ __forceinline__ void ldm_x4(uint32_t* r, const __half* p) {
    asm volatile("ldmatrix.sync.aligned.m8n8.x4.shared.b16 {%0,%1,%2,%3}, [%4];\n"
                 : "=r"(r[0]), "=r"(r[1]), "=r"(r[2]), "=r"(r[3])
                 : "r"(smem_u32(p)));
}
__device__ __forceinline__ void mma_f16(uint32_t* c, const uint32_t* a,
                                        const uint32_t* b) {
    asm volatile("mma.sync.aligned.m16n8k16.row.col.f16.f16.f16.f16 "
                 "{%0,%1}, {%2,%3,%4,%5}, {%6,%7}, {%0,%1};\n"
                 : "+r"(c[0]), "+r"(c[1])
                 : "r"(a[0]), "r"(a[1]), "r"(a[2]), "r"(a[3]),
                   "r"(b[0]), "r"(b[1]));
}
// XOR-swizzled half offset for (row, 16B-chunk c8) in a [rows][64]-half tile.
__device__ __forceinline__ int swz(int row, int c8) {
    return row * 64 + ((c8 ^ (row & 7)) << 3);
}

// ---------------------------------------------------------------------------
// Persistent HMMA(f16-acc) GEMM-min. 444 CTAs, 3/SM, 6272 items.
// R15 structure (single barrier/chunk, prefetch between ks=0 and ks=1) plus
// CROSS-ITEM chunk-0 prefetch: at kc==NKC-1 the prefetch targets the next
// item's chunk 0 (parity-correct: buffer 0), so the cp.async ring never
// drains and the epilogue overlaps the next item's first loads. The per-item
// prologue reduces to a single pre-loop issue.
// ---------------------------------------------------------------------------
__device__ __forceinline__ void frags_step(uint32_t a[2][4], uint32_t b[8][2],
                                           const __half* Asb, const __half* Bsb,
                                           int ks, int wm, int wn,
                                           int arow, int acbit) {
    int c8 = ks * 2 + acbit;
#pragma unroll
    for (int mt = 0; mt < 2; ++mt) {
        int row = wm * 32 + mt * 16 + arow;
        ldm_x4(a[mt], Asb + swz(row, c8));
    }
#pragma unroll
    for (int tp = 0; tp < 4; ++tp) {
        uint32_t r[4];
        int row = wn * 64 + tp * 16 + arow;
        ldm_x4(r, Bsb + swz(row, c8));
        b[2 * tp][0] = r[0];  b[2 * tp][1] = r[2];
        b[2 * tp + 1][0] = r[1]; b[2 * tp + 1][1] = r[3];
    }
}

__global__ __launch_bounds__(THREADS, 3)
void gemm_min_kernel() {
    extern __shared__ __align__(16) char smem_raw[];
    __half* As = (__half*)smem_raw;                   // 2 x [128][64]
    __half* Bs = As + 2 * BM * 64;                    // 2 x [128][64]

    const int tid = threadIdx.x;
    const int lane = tid & 31, warp = tid >> 5;
    const int wm = warp >> 1, wn = warp & 1;          // 4(M) x 2(N) warps

    const int arow  = (lane & 7) + ((lane >> 3) & 1) * 8;
    const int acbit = (lane >> 4) & 1;

    // hoisted producer addressing
    const int c8p  = tid & 7;
    const int rp0  = tid >> 3;
    const int offP = swz(rp0, c8p);
    __half* const dA0 = As + offP;
    __half* const dB0 = Bs + offP;

    // pre-loop prologue: first item's chunk 0 -> buffer 0
    {
        const int it0 = blockIdx.x;
        const __half* a0 = g_A  + (size_t)((it0 >> 5) * BM + rp0) * DD + c8p * 8;
        const __half* b0 = g_Bc + (size_t)((it0 & 31) * BN + rp0) * DD + c8p * 8;
#pragma unroll
        for (int t = 0; t < 4; ++t) {
            cp16(dA0 + t * 2048, a0 + (size_t)t * 32 * DD);
            cp16(dB0 + t * 2048, b0 + (size_t)t * 32 * DD);
        }
        cp_commit();
    }

    for (int it = blockIdx.x; it < NITEMS; it += GRID) {
        const int m0 = (it >> 5) * BM;
        const int p0 = (it & 31) * BN;

        const __half* const aBase = g_A  + (size_t)(m0 + rp0) * DD + c8p * 8;
        const __half* const bBase = g_Bc + (size_t)(p0 + rp0) * DD + c8p * 8;

        uint32_t acc[2][8][2];                        // f16x2 accumulators
#pragma unroll
        for (int i = 0; i < 2; ++i)
#pragma unroll
            for (int j = 0; j < 8; ++j) { acc[i][j][0] = 0u; acc[i][j][1] = 0u; }

#pragma unroll 1
        for (int kc = 0; kc < NKC; ++kc) {
            cp_wait<0>();          // chunk kc fully arrived
            __syncthreads();       // all warps done reading buffer (kc-1)&1

            const __half* Asb = As + (kc & 1) * BM * 64;
            const __half* Bsb = Bs + (kc & 1) * BN * 64;

            // ks=0: start the tensor critical path FIRST
            uint32_t a[2][4], b[8][2];
            frags_step(a, b, Asb, Bsb, 0, wm, wn, arow, acbit);
#pragma unroll
            for (int mt = 0; mt < 2; ++mt)
#pragma unroll
                for (int j = 0; j < 8; ++j)
                    mma_f16(acc[mt][j], a[mt], b[j]);

            // prefetch (issue overlaps tensor-busy cycles):
            //  - intra-item: chunk kc+1 into buffer (kc+1)&1
            //  - last chunk: NEXT item's chunk 0 into buffer 0 (same parity)
            if (kc + 1 < NKC) {
                const int bufo = ((kc + 1) & 1) * (BM * 64);
                const __half* ag = aBase + (kc + 1) * BK;
                const __half* bg = bBase + (kc + 1) * BK;
#pragma unroll
                for (int t = 0; t < 4; ++t) {
                    cp16(dA0 + bufo + t * 2048, ag + (size_t)t * 32 * DD);
                    cp16(dB0 + bufo + t * 2048, bg + (size_t)t * 32 * DD);
                }
                cp_commit();
            } else if (it + GRID < NITEMS) {
                const int nit = it + GRID;
                const __half* ag = g_A  + (size_t)((nit >> 5) * BM + rp0) * DD + c8p * 8;
                const __half* bg = g_Bc + (size_t)((nit & 31) * BN + rp0) * DD + c8p * 8;
#pragma unroll
                for (int t = 0; t < 4; ++t) {
                    cp16(dA0 + t * 2048, ag + (size_t)t * 32 * DD);
                    cp16(dB0 + t * 2048, bg + (size_t)t * 32 * DD);
                }
                cp_commit();
            }

            // ks = 1..3
#pragma unroll
            for (int ks = 1; ks < BK / 16; ++ks) {
                frags_step(a, b, Asb, Bsb, ks, wm, wn, arow, acbit);
#pragma unroll
                for (int mt = 0; mt < 2; ++mt)
#pragma unroll
                    for (int j = 0; j < 8; ++j)
                        mma_f16(acc[mt][j], a[mt], b[j]);
            }
            // no trailing barrier: next chunk's top barrier provides safety
        }

        // epilogue (overlaps next item's chunk-0 loads already in flight)
        float rmin[2][2] = {{3.4e38f, 3.4e38f}, {3.4e38f, 3.4e38f}};
#pragma unroll
        for (int j = 0; j < 8; ++j) {
            int col = p0 + wn * 64 + j * 8 + (lane & 3) * 2;
            float nc0 = g_nB[col], nc1 = g_nB[col + 1];
#pragma unroll
            for (int mt = 0; mt < 2; ++mt) {
                float2 lo = __half22float2(*(__half2*)&acc[mt][j][0]); // row r
                float2 hi = __half22float2(*(__half2*)&acc[mt][j][1]); // row r+8
                float v0 = fminf(nc0 - 2.f * lo.x, nc1 - 2.f * lo.y);
                float v1 = fminf(nc0 - 2.f * hi.x, nc1 - 2.f * hi.y);
                rmin[mt][0] = fminf(rmin[mt][0], v0);
                rmin[mt][1] = fminf(rmin[mt][1], v1);
            }
        }
#pragma unroll
        for (int mt = 0; mt < 2; ++mt)
#pragma unroll
            for (int h = 0; h < 2; ++h) {
                float v = rmin[mt][h];
                v = fminf(v, __shfl_xor_sync(0xffffffffu, v, 1));
                v = fminf(v, __shfl_xor_sync(0xffffffffu, v, 2));
                rmin[mt][h] = v;
            }
        if ((lane & 3) == 0) {
            int q = lane >> 2;
#pragma unroll
            for (int mt = 0; mt < 2; ++mt)
#pragma unroll
                for (int h = 0; h < 2; ++h) {
                    int m = m0 + wm * 32 + mt * 16 + h * 8 + q;
                    float d2 = fmaxf(g_nA[m] + rmin[mt][h], 0.f);
                    atomicMin(&g_min[m], __float_as_uint(d2));
                }
        }
    }
}

// ---------------------------------------------------------------------------
// Final: sqrt of the folded min distance^2.
// ---------------------------------------------------------------------------
__global__ void sqrt_kernel(float* __restrict__ out, int offset) {
    int m = blockIdx.x * blockDim.x + threadIdx.x;
    if (m < MM) out[offset + m] = sqrtf(__uint_as_float(g_min[m]));
}

// ---------------------------------------------------------------------------
extern "C" void kernel_launch(void* const* d_in, const int* in_sizes, int n_in,
                              void* d_out, int out_size) {
    const float* embeds = (const float*)d_in[0];
    const float* cents  = (const float*)d_in[1];
    if (n_in >= 2 && in_sizes[0] == PP * DD && in_sizes[1] == MM * DD) {
        embeds = (const float*)d_in[1];
        cents  = (const float*)d_in[0];
    }
    float* out = (float*)d_out;
    int loss_elems = out_size - MM;
    if (loss_elems < 0) loss_elems = 0;

    cudaFuncSetAttribute(gemm_min_kernel,
                         cudaFuncAttributeMaxDynamicSharedMemorySize, SMEM_BYTES);

    prep_kernel<<<MM + PP, PT>>>(embeds, cents, out, loss_elems);
    gemm_min_kernel<<<GRID, THREADS, SMEM_BYTES>>>();
    sqrt_kernel<<<(MM + 255) / 256, 256>>>(out, loss_elems);
}